// round 15
// baseline (speedup 1.0000x reference)
#include <cuda_runtime.h>
#include <cuda_bf16.h>
#include <cstdint>
#include <cstddef>

#define NWSEQ 1024
#define TW    64
#define MWORD (NWSEQ*TW)
#define NDOC  32
#define TSENT 32
#define MSENT (NDOC*TSENT)
#define HD2   512
#define HD3   768
#define EDIM  200
#define VMAX  50000
#define EKP   224

typedef unsigned long long ull;
typedef unsigned short u16;
typedef __nv_bfloat16 bf16;

// scratch
__device__ float g_xg [2ull*MWORD*HD3];     // word input gates; later partial scores
__device__ float g_xg2[2ull*MSENT*HD3];
__device__ float4 g_whp [2*256*256 + 1024];
__device__ float4 g_whp2[2*256*256 + 1024];
// bf16-split planes (A row-major [row][KP]; weights row-major [KP][N])
__device__ bf16 g_embC_hi[(size_t)VMAX*EKP], g_embC_lo[(size_t)VMAX*EKP];
__device__ bf16 g_wxC_hi [2*EKP*HD3],  g_wxC_lo [2*EKP*HD3];
__device__ bf16 g_linC_hi[HD2*HD2],    g_linC_lo[HD2*HD2];
__device__ bf16 g_swxC_hi[2*HD2*HD3],  g_swxC_lo[2*HD2*HD3];
__device__ bf16 g_slinC_hi[HD2*HD2],   g_slinC_lo[HD2*HD2];
__device__ bf16 g_hb_hi[(size_t)MWORD*HD2], g_hb_lo[(size_t)MWORD*HD2];
__device__ bf16 g_sb_hi[(size_t)MSENT*HD2], g_sb_lo[(size_t)MSENT*HD2];
__device__ bf16 g_h2b_hi[(size_t)MSENT*HD2], g_h2b_lo[(size_t)MSENT*HD2];

__device__ __forceinline__ ull pk2(float lo, float hi){
    ull r; asm("mov.b64 %0, {%1,%2};" : "=l"(r) : "f"(lo), "f"(hi)); return r;
}
__device__ __forceinline__ float2 upk2(ull v){
    float2 f; asm("mov.b64 {%0,%1}, %2;" : "=f"(f.x), "=f"(f.y) : "l"(v)); return f;
}
__device__ __forceinline__ ull fma2(ull a, ull b, ull c){
    ull d; asm("fma.rn.f32x2 %0, %1, %2, %3;" : "=l"(d) : "l"(a), "l"(b), "l"(c)); return d;
}
__device__ __forceinline__ float fsig(float x){ return 1.0f/(1.0f + __expf(-x)); }
__device__ __forceinline__ float ftanh(float x){ return 1.0f - 2.0f/(__expf(2.0f*x) + 1.0f); }

__device__ __forceinline__ void ldsm4(uint32_t& r0, uint32_t& r1, uint32_t& r2, uint32_t& r3, uint32_t addr){
    asm volatile("ldmatrix.sync.aligned.m8n8.x4.shared.b16 {%0,%1,%2,%3}, [%4];"
        : "=r"(r0), "=r"(r1), "=r"(r2), "=r"(r3) : "r"(addr));
}
__device__ __forceinline__ void ldsm4t(uint32_t& r0, uint32_t& r1, uint32_t& r2, uint32_t& r3, uint32_t addr){
    asm volatile("ldmatrix.sync.aligned.m8n8.x4.trans.shared.b16 {%0,%1,%2,%3}, [%4];"
        : "=r"(r0), "=r"(r1), "=r"(r2), "=r"(r3) : "r"(addr));
}
__device__ __forceinline__ void mma16816(float* d, uint32_t a0, uint32_t a1, uint32_t a2, uint32_t a3,
                                         uint32_t b0, uint32_t b1){
    asm volatile("mma.sync.aligned.m16n8k16.row.col.f32.bf16.bf16.f32 "
        "{%0,%1,%2,%3}, {%4,%5,%6,%7}, {%8,%9}, {%0,%1,%2,%3};"
        : "+f"(d[0]), "+f"(d[1]), "+f"(d[2]), "+f"(d[3])
        : "r"(a0), "r"(a1), "r"(a2), "r"(a3), "r"(b0), "r"(b1));
}
__device__ __forceinline__ void cpa16(uint32_t dst, const void* src){
    asm volatile("cp.async.cg.shared.global [%0], [%1], 16;" :: "r"(dst), "l"(src) : "memory");
}
#define CPA_COMMIT() asm volatile("cp.async.commit_group;" ::: "memory")
#define CPA_WAIT1()  asm volatile("cp.async.wait_group 1;" ::: "memory")
#define CPA_WAIT0()  asm volatile("cp.async.wait_group 0;" ::: "memory")

// ---------------------------------------------------------------------------
// One-time converters
// ---------------------------------------------------------------------------
__global__ void conv_splitA_kernel(const float* __restrict__ src,
                                   bf16* __restrict__ hi, bf16* __restrict__ lo,
                                   int K, int KP, long long total){
    long long i = (long long)blockIdx.x * blockDim.x + threadIdx.x;
    if (i >= total) return;
    int col = (int)(i % KP);
    long long row = i / KP;
    float v = (col < K) ? src[row * K + col] : 0.f;
    bf16 h = __float2bfloat16_rn(v);
    hi[i] = h;
    lo[i] = __float2bfloat16_rn(v - __bfloat162float(h));
}
// All six weight matrices in one launch (blockIdx.y = region; shapes compile-time)
__global__ void conv_weights_kernel(
    const float* __restrict__ wxf, const float* __restrict__ wxb,
    const float* __restrict__ lin,
    const float* __restrict__ swxf, const float* __restrict__ swxb,
    const float* __restrict__ slin,
    bf16* __restrict__ wxH, bf16* __restrict__ wxL,
    bf16* __restrict__ linH, bf16* __restrict__ linL,
    bf16* __restrict__ swxH, bf16* __restrict__ swxL,
    bf16* __restrict__ slinH, bf16* __restrict__ slinL)
{
    int r = blockIdx.y;
    long long i = (long long)blockIdx.x * blockDim.x + threadIdx.x;
    const float* src; bf16 *hi, *lo; int K, KP, N;
    switch (r) {
      case 0: src = wxf;  hi = wxH;            lo = wxL;            K = EDIM; KP = EKP; N = HD3; break;
      case 1: src = wxb;  hi = wxH + EKP*HD3;  lo = wxL + EKP*HD3;  K = EDIM; KP = EKP; N = HD3; break;
      case 2: src = lin;  hi = linH;           lo = linL;           K = HD2;  KP = HD2; N = HD2; break;
      case 3: src = swxf; hi = swxH;           lo = swxL;           K = HD2;  KP = HD2; N = HD3; break;
      case 4: src = swxb; hi = swxH + HD2*HD3; lo = swxL + HD2*HD3; K = HD2;  KP = HD2; N = HD3; break;
      default:src = slin; hi = slinH;          lo = slinL;          K = HD2;  KP = HD2; N = HD2; break;
    }
    long long tot = (long long)KP * N;
    if (i >= tot) return;
    int n = (int)(i % N), k = (int)(i / N);
    float v = (k < K) ? src[(size_t)k * N + n] : 0.f;
    bf16 h = __float2bfloat16_rn(v);
    hi[i] = h;
    lo[i] = __float2bfloat16_rn(v - __bfloat162float(h));
}
__global__ void repack_wh_kernel(const float* __restrict__ Whf,
                                 const float* __restrict__ Whb,
                                 float4* __restrict__ whp){
    int k = blockIdx.x, d = blockIdx.y, j = threadIdx.x;
    const float* Wh = d ? Whb : Whf;
    float4 v;
    v.x = Wh[(size_t)k*HD3 + j];
    v.y = Wh[(size_t)k*HD3 + 256 + j];
    v.z = Wh[(size_t)k*HD3 + 512 + j];
    v.w = 0.f;
    whp[((size_t)d*256 + k)*256 + j] = v;
}

// ---------------------------------------------------------------------------
// bf16-split mma.sync GEMM v4. Block tile 128x128, k-tile 32, warps 4(m)x2(n).
// 3-stage cp.async ring, ONE sync per tile, copies issued BEFORE compute:
//  iter t: wait(tile t) / sync / issue t+2 / compute t.
// ---------------------------------------------------------------------------
#define ASTR 40     // u16 per A smem row (32 + 8 pad)
#define BSTR 136    // u16 per B smem row (128 + 8 pad)
#define OFF_AHI 0
#define OFF_ALO 10240
#define OFF_BHI 20480
#define OFF_BLO 29184
#define BUFSZ   37888
#define GSMEM   (3*BUFSZ)
template<bool SCORE>
__global__ __launch_bounds__(256,2) void mma2_kernel(
    const bf16* __restrict__ Ahi, const bf16* __restrict__ Alo,
    const int* __restrict__ gather, int KP,
    const bf16* __restrict__ Bhi, const bf16* __restrict__ Blo,
    const float* __restrict__ bf_, const float* __restrict__ bb_,
    const float* __restrict__ ctx,
    float* __restrict__ out, int M, int nyPerDir)
{
    extern __shared__ __align__(16) char dsm[];
    uint32_t sb;
    asm("{ .reg .u64 t; cvta.to.shared.u64 t, %1; cvt.u32.u64 %0, t; }" : "=r"(sb) : "l"(dsm));
    int tid = threadIdx.x;
    int w = tid >> 5, lane = tid & 31;
    int g = lane >> 2, t4 = lane & 3;
    int mg = w & 3, ng = w >> 2;
    int m0 = blockIdx.x * 128;
    int dir = blockIdx.y / nyPerDir;
    int jb  = blockIdx.y % nyPerDir;
    int j0  = jb * 128;
    int ldw = nyPerDir * 128;
    const bf16* Bh = Bhi + (size_t)dir * KP * ldw;
    const bf16* Bl = Blo + (size_t)dir * KP * ldw;
    const float* bias = dir ? bb_ : bf_;

    int arow = tid >> 1, ahalf = tid & 1;
    size_t arbase = (size_t)(gather ? gather[m0 + arow] : (m0 + arow)) * KP + ahalf * 16;
    uint32_t adst = (uint32_t)(arow * ASTR + ahalf * 16) * 2;
    int bkr = tid >> 3, bc0 = (tid & 7) * 16;
    size_t bo = (size_t)bkr * ldw + j0 + bc0;
    uint32_t bdst = (uint32_t)(bkr * BSTR + bc0) * 2;

    float acc[2][8][4];
#pragma unroll
    for (int mt = 0; mt < 2; mt++)
#pragma unroll
        for (int n = 0; n < 8; n++){ acc[mt][n][0]=acc[mt][n][1]=acc[mt][n][2]=acc[mt][n][3]=0.f; }

    uint32_t aOff0 = ((mg*32 + (lane & 15)) * ASTR + (lane >> 4) * 8) * 2;
    uint32_t aOff1 = ((mg*32 + 16 + (lane & 15)) * ASTR + (lane >> 4) * 8) * 2;
    uint32_t bT = ((lane & 15) * BSTR + (lane >> 4) * 8) * 2 + ng * 128;

    int nt = KP / 32;

#define ISSUE_TILE(BUFB, K0) do { \
    const bf16* _pa = Ahi + arbase + (K0); \
    const bf16* _pl = Alo + arbase + (K0); \
    cpa16((BUFB) + OFF_AHI + adst,      _pa); \
    cpa16((BUFB) + OFF_AHI + adst + 16, _pa + 8); \
    cpa16((BUFB) + OFF_ALO + adst,      _pl); \
    cpa16((BUFB) + OFF_ALO + adst + 16, _pl + 8); \
    const bf16* _pbh = Bh + bo + (size_t)(K0) * ldw; \
    const bf16* _pbl = Bl + bo + (size_t)(K0) * ldw; \
    cpa16((BUFB) + OFF_BHI + bdst,      _pbh); \
    cpa16((BUFB) + OFF_BHI + bdst + 16, _pbh + 8); \
    cpa16((BUFB) + OFF_BLO + bdst,      _pbl); \
    cpa16((BUFB) + OFF_BLO + bdst + 16, _pbl + 8); \
} while(0)

    ISSUE_TILE(sb, 0); CPA_COMMIT();
    if (nt > 1){ ISSUE_TILE(sb + BUFSZ, 32); CPA_COMMIT(); }

    int bufIdx = 0;
    for (int t = 0; t < nt; t++){
        if (t + 1 < nt) { CPA_WAIT1(); } else { CPA_WAIT0(); }
        __syncthreads();
        // issue NEXT+1 tile first (copies overlap this tile's compute)
        if (t + 2 < nt){
            int nb = bufIdx + 2; if (nb >= 3) nb -= 3;
            ISSUE_TILE(sb + nb * BUFSZ, (t + 2) * 32); CPA_COMMIT();
        }
        uint32_t bufb = sb + bufIdx * BUFSZ;
#pragma unroll
        for (int h = 0; h < 2; h++){
            uint32_t a0h0,a0h1,a0h2,a0h3, a0l0,a0l1,a0l2,a0l3;
            uint32_t a1h0,a1h1,a1h2,a1h3, a1l0,a1l1,a1l2,a1l3;
            ldsm4(a0h0,a0h1,a0h2,a0h3, bufb + OFF_AHI + aOff0 + h*32);
            ldsm4(a0l0,a0l1,a0l2,a0l3, bufb + OFF_ALO + aOff0 + h*32);
            ldsm4(a1h0,a1h1,a1h2,a1h3, bufb + OFF_AHI + aOff1 + h*32);
            ldsm4(a1l0,a1l1,a1l2,a1l3, bufb + OFF_ALO + aOff1 + h*32);
#pragma unroll
            for (int np = 0; np < 4; np++){
                uint32_t ba = bT + h*16*BSTR*2 + np*32;
                uint32_t bh0,bh1,bh2,bh3, bl0,bl1,bl2,bl3;
                ldsm4t(bh0,bh1,bh2,bh3, bufb + OFF_BHI + ba);
                ldsm4t(bl0,bl1,bl2,bl3, bufb + OFF_BLO + ba);
                mma16816(acc[0][2*np],   a0h0,a0h1,a0h2,a0h3, bh0,bh1);
                mma16816(acc[0][2*np],   a0h0,a0h1,a0h2,a0h3, bl0,bl1);
                mma16816(acc[0][2*np],   a0l0,a0l1,a0l2,a0l3, bh0,bh1);
                mma16816(acc[0][2*np+1], a0h0,a0h1,a0h2,a0h3, bh2,bh3);
                mma16816(acc[0][2*np+1], a0h0,a0h1,a0h2,a0h3, bl2,bl3);
                mma16816(acc[0][2*np+1], a0l0,a0l1,a0l2,a0l3, bh2,bh3);
                mma16816(acc[1][2*np],   a1h0,a1h1,a1h2,a1h3, bh0,bh1);
                mma16816(acc[1][2*np],   a1h0,a1h1,a1h2,a1h3, bl0,bl1);
                mma16816(acc[1][2*np],   a1l0,a1l1,a1l2,a1l3, bh0,bh1);
                mma16816(acc[1][2*np+1], a1h0,a1h1,a1h2,a1h3, bh2,bh3);
                mma16816(acc[1][2*np+1], a1h0,a1h1,a1h2,a1h3, bl2,bl3);
                mma16816(acc[1][2*np+1], a1l0,a1l1,a1l2,a1l3, bh2,bh3);
            }
        }
        bufIdx = (bufIdx == 2) ? 0 : bufIdx + 1;
    }
#undef ISSUE_TILE

    if (!SCORE) {
        float* od = out + (size_t)dir * M * ldw;
#pragma unroll
        for (int mt = 0; mt < 2; mt++){
            int r0 = m0 + mg*32 + mt*16 + g;
#pragma unroll
            for (int n = 0; n < 8; n++){
                int c = j0 + ng*64 + n*8 + t4*2;
                float b0 = __ldg(&bias[c]), b1 = __ldg(&bias[c+1]);
                float2 o0{acc[mt][n][0] + b0, acc[mt][n][1] + b1};
                float2 o1{acc[mt][n][2] + b0, acc[mt][n][3] + b1};
                *(float2*)&od[(size_t)r0 * ldw + c]     = o0;
                *(float2*)&od[(size_t)(r0+8) * ldw + c] = o1;
            }
        }
    } else {
#pragma unroll
        for (int mt = 0; mt < 2; mt++){
            float s0 = 0.f, s1 = 0.f;
#pragma unroll
            for (int n = 0; n < 8; n++){
                int c = j0 + ng*64 + n*8 + t4*2;
                float b0 = __ldg(&bias[c]), b1 = __ldg(&bias[c+1]);
                float c0 = __ldg(&ctx[c]),  c1 = __ldg(&ctx[c+1]);
                s0 += ftanh(acc[mt][n][0] + b0)*c0 + ftanh(acc[mt][n][1] + b1)*c1;
                s1 += ftanh(acc[mt][n][2] + b0)*c0 + ftanh(acc[mt][n][3] + b1)*c1;
            }
            s0 += __shfl_xor_sync(0xffffffffu, s0, 1); s0 += __shfl_xor_sync(0xffffffffu, s0, 2);
            s1 += __shfl_xor_sync(0xffffffffu, s1, 1); s1 += __shfl_xor_sync(0xffffffffu, s1, 2);
            if (t4 == 0){
                int r0 = m0 + mg*32 + mt*16 + g;
                int pslot = jb * 2 + ng;
                out[(size_t)pslot * M + r0]     = s0;
                out[(size_t)pslot * M + r0 + 8] = s1;
            }
        }
    }
}

// ---------------------------------------------------------------------------
// GRU scan. Change vs R14: k-loop split at 192 with x-gate LDGs issued in
// between -> ~64 k-iterations of latency cover; x regs live only last quarter.
// ---------------------------------------------------------------------------
template<int T, int G>
__global__ __launch_bounds__(256,2) void gru_scan_kernel(
    const float* __restrict__ xg,
    bf16* __restrict__ hb_hi, bf16* __restrict__ hb_lo,
    const float4* __restrict__ whp,
    const float* __restrict__ bhf, const float* __restrict__ bhb, int NS)
{
    constexpr int P = G / 2;
    __shared__ __align__(16) float sh[2][256][G];
    int j = threadIdx.x;
    int gpd = NS / G;
    int d  = blockIdx.x / gpd;
    int n0 = (blockIdx.x % gpd) * G;
    const float* bh = d ? bhb : bhf;
    const float4* Wp = whp + (size_t)d * 256 * 256;
    const float* xgd = xg + (size_t)d * NS * T * HD3;
    float bhr = bh[j], bhz = bh[256 + j], bhn = bh[512 + j];
    float hprev[G];
#pragma unroll
    for (int gg = 0; gg < G; gg++){ hprev[gg] = 0.f; sh[0][j][gg] = 0.f; }
    __syncthreads();

    int cur = 0;
    for (int tt = 0; tt < T; tt++) {
        int t = d ? (T - 1 - tt) : tt;
        ull ar[P], az[P], an[P];
#pragma unroll
        for (int p = 0; p < P; p++){
            ar[p] = pk2(bhr, bhr); az[p] = pk2(bhz, bhz); an[p] = pk2(bhn, bhn);
        }
        float4 w = Wp[j];

#define SCAN_K_BODY \
        { \
            float4 wnext = Wp[(size_t)(k + 1) * 256 + j]; \
            ull wr2 = pk2(w.x, w.x), wz2 = pk2(w.y, w.y), wn2 = pk2(w.z, w.z); \
            if constexpr ((G & 3) == 0) { \
                _Pragma("unroll") \
                for (int q = 0; q < P/2; q++){ \
                    ulonglong2 hq = *(const ulonglong2*)&sh[cur][k][4*q]; \
                    ar[2*q]   = fma2(wr2, hq.x, ar[2*q]); \
                    az[2*q]   = fma2(wz2, hq.x, az[2*q]); \
                    an[2*q]   = fma2(wn2, hq.x, an[2*q]); \
                    ar[2*q+1] = fma2(wr2, hq.y, ar[2*q+1]); \
                    az[2*q+1] = fma2(wz2, hq.y, az[2*q+1]); \
                    an[2*q+1] = fma2(wn2, hq.y, an[2*q+1]); \
                } \
            } else { \
                _Pragma("unroll") \
                for (int p = 0; p < P; p++){ \
                    ull h2 = *(const ull*)&sh[cur][k][2*p]; \
                    ar[p] = fma2(wr2, h2, ar[p]); \
                    az[p] = fma2(wz2, h2, az[p]); \
                    an[p] = fma2(wn2, h2, an[p]); \
                } \
            } \
            w = wnext; \
        }

#pragma unroll 8
        for (int k = 0; k < 192; k++) SCAN_K_BODY

        // x-gate loads issued here: covered by the remaining 64 k-iterations
        float xr[G], xz[G], xn[G];
#pragma unroll
        for (int gg = 0; gg < G; gg++){
            const float* xp = xgd + ((size_t)(n0 + gg) * T + t) * HD3;
            xr[gg] = xp[j]; xz[gg] = xp[256 + j]; xn[gg] = xp[512 + j];
        }

#pragma unroll 8
        for (int k = 192; k < 256; k++) SCAN_K_BODY
#undef SCAN_K_BODY

        int nxt = cur ^ 1;
        float hnew[G];
#pragma unroll
        for (int p = 0; p < P; p++){
            float2 fr = upk2(ar[p]), fz = upk2(az[p]), fn = upk2(an[p]);
#pragma unroll
            for (int e = 0; e < 2; e++){
                int gg = 2*p + e;
                float hr = e ? fr.y : fr.x, hz = e ? fz.y : fz.x, hn = e ? fn.y : fn.x;
                float r = fsig(xr[gg] + hr), z = fsig(xz[gg] + hz);
                float n = ftanh(xn[gg] + r * hn);
                hnew[gg] = (1.f - z) * n + z * hprev[gg];
            }
        }
#pragma unroll
        for (int gg = 0; gg < G; gg++){
            float hv = hnew[gg];
            hprev[gg] = hv;
            sh[nxt][j][gg] = hv;
            size_t off = ((size_t)(n0 + gg) * T + t) * HD2 + d * 256 + j;
            bf16 bhv = __float2bfloat16_rn(hv);
            hb_hi[off] = bhv;
            hb_lo[off] = __float2bfloat16_rn(hv - __bfloat162float(bhv));
        }
        cur = nxt;
        __syncthreads();
    }
}

// ---------------------------------------------------------------------------
// Attention epilogue (proven, unchanged)
// ---------------------------------------------------------------------------
template<int T, bool FINAL>
__global__ __launch_bounds__(256) void attn_epi_kernel(
    const float* __restrict__ part,
    const bf16* __restrict__ h_hi, const bf16* __restrict__ h_lo,
    bf16* __restrict__ outv_hi, bf16* __restrict__ outv_lo,
    const float* __restrict__ outW,
    const float* __restrict__ outb,
    float* __restrict__ outFinal,
    int Mtot)
{
    __shared__ float sScore[T], sX[T], sSrt[T], sAtt[T];
    __shared__ float sTau, sMax;
    __shared__ float sDoc[512];
    int tid = threadIdx.x;
    int n = blockIdx.x;
    size_t hbase = (size_t)n * T * HD2;

    if (tid < T) {
        float s = 0.f;
#pragma unroll
        for (int jb = 0; jb < 8; jb++) s += part[(size_t)jb * Mtot + n * T + tid];
        sScore[tid] = s;
    }
    __syncthreads();
    if (tid == 0) {
        float mx = sScore[0];
        for (int t = 1; t < T; t++) mx = fmaxf(mx, sScore[t]);
        sMax = mx;
    }
    __syncthreads();
    if (tid < T) {
        float x = sScore[tid] - sMax;
        sX[tid] = x;
        int rank = 0;
        for (int u = 0; u < T; u++){
            float xu = sScore[u] - sMax;
            if (xu > x || (xu == x && u < tid)) rank++;
        }
        sSrt[rank] = x;
    }
    __syncthreads();
    if (tid == 0) {
        float cs = -1.f; int supp = 0; float csAt = 0.f;
        for (int k = 0; k < T; k++){
            cs += sSrt[k];
            if ((float)(k + 1) * sSrt[k] > cs) { supp = k + 1; csAt = cs; }
        }
        sTau = csAt / (float)supp;
    }
    __syncthreads();
    if (tid < T) sAtt[tid] = fmaxf(sX[tid] - sTau, 0.f);
    __syncthreads();
    {
        int jj = tid * 2;
        float ax = 0.f, ay = 0.f;
#pragma unroll 8
        for (int t = 0; t < T; t++){
            size_t off = hbase + (size_t)t * HD2 + jj;
            uint32_t ph = *(const uint32_t*)&h_hi[off];
            uint32_t pl = *(const uint32_t*)&h_lo[off];
            __nv_bfloat162 bh = *(__nv_bfloat162*)&ph;
            __nv_bfloat162 bl = *(__nv_bfloat162*)&pl;
            float hx = __bfloat162float(bh.x) + __bfloat162float(bl.x);
            float hy = __bfloat162float(bh.y) + __bfloat162float(bl.y);
            float a = sAtt[t];
            ax += a * hx; ay += a * hy;
        }
        if (FINAL){ sDoc[jj] = ax; sDoc[jj + 1] = ay; }
        else {
            size_t o = (size_t)n * HD2 + jj;
            bf16 hx = __float2bfloat16_rn(ax);
            bf16 hy = __float2bfloat16_rn(ay);
            __nv_bfloat162 hp = __halves2bfloat162(hx, hy);
            __nv_bfloat162 lp = __halves2bfloat162(
                __float2bfloat16_rn(ax - __bfloat162float(hx)),
                __float2bfloat16_rn(ay - __bfloat162float(hy)));
            *(uint32_t*)&outv_hi[o] = *(uint32_t*)&hp;
            *(uint32_t*)&outv_lo[o] = *(uint32_t*)&lp;
        }
    }
    if (FINAL) {
        __syncthreads();
        if (tid < 10) {
            float s = outb[tid];
            for (int jj2 = 0; jj2 < 512; jj2++) s += sDoc[jj2] * outW[jj2 * 10 + tid];
            outFinal[n * 10 + tid] = s;
        }
    }
}

extern "C" void kernel_launch(void* const* d_in, const int* in_sizes, int n_in,
                              void* d_out, int out_size) {
    const int*   tokens  = (const int*)  d_in[0];
    const float* emb     = (const float*)d_in[1];
    const float* w_Wx_f  = (const float*)d_in[2];
    const float* w_Wh_f  = (const float*)d_in[3];
    const float* w_bx_f  = (const float*)d_in[4];
    const float* w_bh_f  = (const float*)d_in[5];
    const float* w_Wx_b  = (const float*)d_in[6];
    const float* w_Wh_b  = (const float*)d_in[7];
    const float* w_bx_b  = (const float*)d_in[8];
    const float* w_bh_b  = (const float*)d_in[9];
    const float* w_lin_W = (const float*)d_in[10];
    const float* w_lin_b = (const float*)d_in[11];
    const float* w_ctx   = (const float*)d_in[12];
    const float* s_Wx_f  = (const float*)d_in[13];
    const float* s_Wh_f  = (const float*)d_in[14];
    const float* s_bx_f  = (const float*)d_in[15];
    const float* s_bh_f  = (const float*)d_in[16];
    const float* s_Wx_b  = (const float*)d_in[17];
    const float* s_Wh_b  = (const float*)d_in[18];
    const float* s_bx_b  = (const float*)d_in[19];
    const float* s_bh_b  = (const float*)d_in[20];
    const float* s_lin_W = (const float*)d_in[21];
    const float* s_lin_b = (const float*)d_in[22];
    const float* s_ctx   = (const float*)d_in[23];
    const float* out_W   = (const float*)d_in[24];
    const float* out_b   = (const float*)d_in[25];
    float* out = (float*)d_out;

    int V = in_sizes[1] / EDIM;

    float *p_xg, *p_xg2;
    float4 *p_whp, *p_whp2;
    bf16 *p_embH, *p_embL, *p_wxH, *p_wxL, *p_linH, *p_linL;
    bf16 *p_swxH, *p_swxL, *p_slinH, *p_slinL;
    bf16 *p_hbH, *p_hbL, *p_sbH, *p_sbL, *p_h2bH, *p_h2bL;
    cudaGetSymbolAddress((void**)&p_xg,   g_xg);
    cudaGetSymbolAddress((void**)&p_xg2,  g_xg2);
    cudaGetSymbolAddress((void**)&p_whp,  g_whp);
    cudaGetSymbolAddress((void**)&p_whp2, g_whp2);
    cudaGetSymbolAddress((void**)&p_embH, g_embC_hi);  cudaGetSymbolAddress((void**)&p_embL, g_embC_lo);
    cudaGetSymbolAddress((void**)&p_wxH,  g_wxC_hi);   cudaGetSymbolAddress((void**)&p_wxL,  g_wxC_lo);
    cudaGetSymbolAddress((void**)&p_linH, g_linC_hi);  cudaGetSymbolAddress((void**)&p_linL, g_linC_lo);
    cudaGetSymbolAddress((void**)&p_swxH, g_swxC_hi);  cudaGetSymbolAddress((void**)&p_swxL, g_swxC_lo);
    cudaGetSymbolAddress((void**)&p_slinH,g_slinC_hi); cudaGetSymbolAddress((void**)&p_slinL,g_slinC_lo);
    cudaGetSymbolAddress((void**)&p_hbH,  g_hb_hi);    cudaGetSymbolAddress((void**)&p_hbL,  g_hb_lo);
    cudaGetSymbolAddress((void**)&p_sbH,  g_sb_hi);    cudaGetSymbolAddress((void**)&p_sbL,  g_sb_lo);
    cudaGetSymbolAddress((void**)&p_h2bH, g_h2b_hi);   cudaGetSymbolAddress((void**)&p_h2bL, g_h2b_lo);

    cudaFuncSetAttribute(mma2_kernel<false>, cudaFuncAttributeMaxDynamicSharedMemorySize, GSMEM);
    cudaFuncSetAttribute(mma2_kernel<true>,  cudaFuncAttributeMaxDynamicSharedMemorySize, GSMEM);

    // 0. one-time conversions / repacks
    repack_wh_kernel<<<dim3(256,2), 256>>>(w_Wh_f, w_Wh_b, p_whp);
    repack_wh_kernel<<<dim3(256,2), 256>>>(s_Wh_f, s_Wh_b, p_whp2);
    {
        long long tot = (long long)V * EKP;
        conv_splitA_kernel<<<(unsigned)((tot + 255) / 256), 256>>>(emb, p_embH, p_embL, EDIM, EKP, tot);
    }
    conv_weights_kernel<<<dim3((HD2*HD3 + 255)/256, 6), 256>>>(
        w_Wx_f, w_Wx_b, w_lin_W, s_Wx_f, s_Wx_b, s_lin_W,
        p_wxH, p_wxL, p_linH, p_linL, p_swxH, p_swxL, p_slinH, p_slinL);
    // 1. word input gates (embedding gather fused)
    mma2_kernel<false><<<dim3(MWORD/128, 12), 256, GSMEM>>>(
        p_embH, p_embL, tokens, EKP, p_wxH, p_wxL, w_bx_f, w_bx_b, nullptr, p_xg, MWORD, 6);
    // 2. word BiGRU scan
    gru_scan_kernel<TW, 8><<<(NWSEQ/8)*2, 256>>>(
        p_xg, p_hbH, p_hbL, p_whp, w_bh_f, w_bh_b, NWSEQ);
    // 3. word rep GEMM fused into scores (partials into g_xg: 8 slots)
    mma2_kernel<true><<<dim3(MWORD/128, 4), 256, GSMEM>>>(
        p_hbH, p_hbL, nullptr, HD2, p_linH, p_linL, w_lin_b, w_lin_b, w_ctx, p_xg, MWORD, 4);
    // 4. word attention epilogue -> sentence vectors (bf16-split direct)
    attn_epi_kernel<TW, false><<<NWSEQ, 256>>>(
        p_xg, p_hbH, p_hbL, p_sbH, p_sbL, nullptr, nullptr, nullptr, MWORD);
    // 5. sentence input gates
    mma2_kernel<false><<<dim3(MSENT/128, 12), 256, GSMEM>>>(
        p_sbH, p_sbL, nullptr, HD2, p_swxH, p_swxL, s_bx_f, s_bx_b, nullptr, p_xg2, MSENT, 6);
    // 6. sentence BiGRU scan
    gru_scan_kernel<TSENT, 2><<<(NDOC/2)*2, 256>>>(
        p_xg2, p_h2bH, p_h2bL, p_whp2, s_bh_f, s_bh_b, NDOC);
    // 7. sentence rep+score GEMM (partials into g_xg2)
    mma2_kernel<true><<<dim3(MSENT/128, 4), 256, GSMEM>>>(
        p_h2bH, p_h2bL, nullptr, HD2, p_slinH, p_slinL, s_lin_b, s_lin_b, s_ctx, p_xg2, MSENT, 4);
    // 8. sentence attention + final classifier
    attn_epi_kernel<TSENT, true><<<NDOC, 256>>>(
        p_xg2, p_h2bH, p_h2bL, nullptr, nullptr, out_W, out_b, out, MSENT);
}

// round 16
// speedup vs baseline: 1.0430x; 1.0430x over previous
#include <cuda_runtime.h>
#include <cuda_bf16.h>
#include <cstdint>
#include <cstddef>

#define NWSEQ 1024
#define TW    64
#define MWORD (NWSEQ*TW)
#define NDOC  32
#define TSENT 32
#define MSENT (NDOC*TSENT)
#define HD2   512
#define HD3   768
#define EDIM  200
#define VMAX  50000
#define EKP   224

typedef unsigned long long ull;
typedef unsigned short u16;
typedef __nv_bfloat16 bf16;

// scratch
__device__ float g_xg [2ull*MWORD*HD3];     // word input gates; later partial scores
__device__ float g_xg2[2ull*MSENT*HD3];
__device__ float4 g_whp [2*256*256 + 1024];
__device__ float4 g_whp2[2*256*256 + 1024];
// bf16-split planes (A row-major [row][KP]; weights row-major [KP][N])
__device__ bf16 g_embC_hi[(size_t)VMAX*EKP], g_embC_lo[(size_t)VMAX*EKP];
__device__ bf16 g_wxC_hi [2*EKP*HD3],  g_wxC_lo [2*EKP*HD3];
__device__ bf16 g_linC_hi[HD2*HD2],    g_linC_lo[HD2*HD2];
__device__ bf16 g_swxC_hi[2*HD2*HD3],  g_swxC_lo[2*HD2*HD3];
__device__ bf16 g_slinC_hi[HD2*HD2],   g_slinC_lo[HD2*HD2];
__device__ bf16 g_hb_hi[(size_t)MWORD*HD2], g_hb_lo[(size_t)MWORD*HD2];
__device__ bf16 g_sb_hi[(size_t)MSENT*HD2], g_sb_lo[(size_t)MSENT*HD2];
__device__ bf16 g_h2b_hi[(size_t)MSENT*HD2], g_h2b_lo[(size_t)MSENT*HD2];

__device__ __forceinline__ ull pk2(float lo, float hi){
    ull r; asm("mov.b64 %0, {%1,%2};" : "=l"(r) : "f"(lo), "f"(hi)); return r;
}
__device__ __forceinline__ float2 upk2(ull v){
    float2 f; asm("mov.b64 {%0,%1}, %2;" : "=f"(f.x), "=f"(f.y) : "l"(v)); return f;
}
__device__ __forceinline__ ull fma2(ull a, ull b, ull c){
    ull d; asm("fma.rn.f32x2 %0, %1, %2, %3;" : "=l"(d) : "l"(a), "l"(b), "l"(c)); return d;
}
__device__ __forceinline__ float fsig(float x){ return 1.0f/(1.0f + __expf(-x)); }
__device__ __forceinline__ float ftanh(float x){ return 1.0f - 2.0f/(__expf(2.0f*x) + 1.0f); }

__device__ __forceinline__ void ldsm4(uint32_t& r0, uint32_t& r1, uint32_t& r2, uint32_t& r3, uint32_t addr){
    asm volatile("ldmatrix.sync.aligned.m8n8.x4.shared.b16 {%0,%1,%2,%3}, [%4];"
        : "=r"(r0), "=r"(r1), "=r"(r2), "=r"(r3) : "r"(addr));
}
__device__ __forceinline__ void ldsm4t(uint32_t& r0, uint32_t& r1, uint32_t& r2, uint32_t& r3, uint32_t addr){
    asm volatile("ldmatrix.sync.aligned.m8n8.x4.trans.shared.b16 {%0,%1,%2,%3}, [%4];"
        : "=r"(r0), "=r"(r1), "=r"(r2), "=r"(r3) : "r"(addr));
}
__device__ __forceinline__ void mma16816(float* d, uint32_t a0, uint32_t a1, uint32_t a2, uint32_t a3,
                                         uint32_t b0, uint32_t b1){
    asm volatile("mma.sync.aligned.m16n8k16.row.col.f32.bf16.bf16.f32 "
        "{%0,%1,%2,%3}, {%4,%5,%6,%7}, {%8,%9}, {%0,%1,%2,%3};"
        : "+f"(d[0]), "+f"(d[1]), "+f"(d[2]), "+f"(d[3])
        : "r"(a0), "r"(a1), "r"(a2), "r"(a3), "r"(b0), "r"(b1));
}
__device__ __forceinline__ void cpa16(uint32_t dst, const void* src){
    asm volatile("cp.async.cg.shared.global [%0], [%1], 16;" :: "r"(dst), "l"(src) : "memory");
}
#define CPA_COMMIT() asm volatile("cp.async.commit_group;" ::: "memory")
#define CPA_WAIT1()  asm volatile("cp.async.wait_group 1;" ::: "memory")
#define CPA_WAIT0()  asm volatile("cp.async.wait_group 0;" ::: "memory")

// ---------------------------------------------------------------------------
// One-time converters
// ---------------------------------------------------------------------------
__global__ void conv_splitA_kernel(const float* __restrict__ src,
                                   bf16* __restrict__ hi, bf16* __restrict__ lo,
                                   int K, int KP, long long total){
    long long i = (long long)blockIdx.x * blockDim.x + threadIdx.x;
    if (i >= total) return;
    int col = (int)(i % KP);
    long long row = i / KP;
    float v = (col < K) ? src[row * K + col] : 0.f;
    bf16 h = __float2bfloat16_rn(v);
    hi[i] = h;
    lo[i] = __float2bfloat16_rn(v - __bfloat162float(h));
}
// All six weight matrices in one launch (blockIdx.y = region; shapes compile-time)
__global__ void conv_weights_kernel(
    const float* __restrict__ wxf, const float* __restrict__ wxb,
    const float* __restrict__ lin,
    const float* __restrict__ swxf, const float* __restrict__ swxb,
    const float* __restrict__ slin,
    bf16* __restrict__ wxH, bf16* __restrict__ wxL,
    bf16* __restrict__ linH, bf16* __restrict__ linL,
    bf16* __restrict__ swxH, bf16* __restrict__ swxL,
    bf16* __restrict__ slinH, bf16* __restrict__ slinL)
{
    int r = blockIdx.y;
    long long i = (long long)blockIdx.x * blockDim.x + threadIdx.x;
    const float* src; bf16 *hi, *lo; int K, KP, N;
    switch (r) {
      case 0: src = wxf;  hi = wxH;            lo = wxL;            K = EDIM; KP = EKP; N = HD3; break;
      case 1: src = wxb;  hi = wxH + EKP*HD3;  lo = wxL + EKP*HD3;  K = EDIM; KP = EKP; N = HD3; break;
      case 2: src = lin;  hi = linH;           lo = linL;           K = HD2;  KP = HD2; N = HD2; break;
      case 3: src = swxf; hi = swxH;           lo = swxL;           K = HD2;  KP = HD2; N = HD3; break;
      case 4: src = swxb; hi = swxH + HD2*HD3; lo = swxL + HD2*HD3; K = HD2;  KP = HD2; N = HD3; break;
      default:src = slin; hi = slinH;          lo = slinL;          K = HD2;  KP = HD2; N = HD2; break;
    }
    long long tot = (long long)KP * N;
    if (i >= tot) return;
    int n = (int)(i % N), k = (int)(i / N);
    float v = (k < K) ? src[(size_t)k * N + n] : 0.f;
    bf16 h = __float2bfloat16_rn(v);
    hi[i] = h;
    lo[i] = __float2bfloat16_rn(v - __bfloat162float(h));
}
__global__ void repack_wh_kernel(const float* __restrict__ Whf,
                                 const float* __restrict__ Whb,
                                 float4* __restrict__ whp){
    int k = blockIdx.x, d = blockIdx.y, j = threadIdx.x;
    const float* Wh = d ? Whb : Whf;
    float4 v;
    v.x = Wh[(size_t)k*HD3 + j];
    v.y = Wh[(size_t)k*HD3 + 256 + j];
    v.z = Wh[(size_t)k*HD3 + 512 + j];
    v.w = 0.f;
    whp[((size_t)d*256 + k)*256 + j] = v;
}

// ---------------------------------------------------------------------------
// bf16-split mma.sync GEMM (R14-proven v3). Block tile 128x128, k-tile 32,
// warps 4(m)x2(n). 3-stage cp.async ring, ONE sync per tile:
//  iter t: wait(tile t) / sync / compute buf[t%3] / issue tile t+2.
// ---------------------------------------------------------------------------
#define ASTR 40     // u16 per A smem row (32 + 8 pad)
#define BSTR 136    // u16 per B smem row (128 + 8 pad)
#define OFF_AHI 0
#define OFF_ALO 10240
#define OFF_BHI 20480
#define OFF_BLO 29184
#define BUFSZ   37888
#define GSMEM   (3*BUFSZ)
template<bool SCORE>
__global__ __launch_bounds__(256,2) void mma2_kernel(
    const bf16* __restrict__ Ahi, const bf16* __restrict__ Alo,
    const int* __restrict__ gather, int KP,
    const bf16* __restrict__ Bhi, const bf16* __restrict__ Blo,
    const float* __restrict__ bf_, const float* __restrict__ bb_,
    const float* __restrict__ ctx,
    float* __restrict__ out, int M, int nyPerDir)
{
    extern __shared__ __align__(16) char dsm[];
    uint32_t sb;
    asm("{ .reg .u64 t; cvta.to.shared.u64 t, %1; cvt.u32.u64 %0, t; }" : "=r"(sb) : "l"(dsm));
    int tid = threadIdx.x;
    int w = tid >> 5, lane = tid & 31;
    int g = lane >> 2, t4 = lane & 3;
    int mg = w & 3, ng = w >> 2;
    int m0 = blockIdx.x * 128;
    int dir = blockIdx.y / nyPerDir;
    int jb  = blockIdx.y % nyPerDir;
    int j0  = jb * 128;
    int ldw = nyPerDir * 128;
    const bf16* Bh = Bhi + (size_t)dir * KP * ldw;
    const bf16* Bl = Blo + (size_t)dir * KP * ldw;
    const float* bias = dir ? bb_ : bf_;

    int arow = tid >> 1, ahalf = tid & 1;
    size_t arbase = (size_t)(gather ? gather[m0 + arow] : (m0 + arow)) * KP + ahalf * 16;
    uint32_t adst = (uint32_t)(arow * ASTR + ahalf * 16) * 2;
    int bkr = tid >> 3, bc0 = (tid & 7) * 16;
    size_t bo = (size_t)bkr * ldw + j0 + bc0;
    uint32_t bdst = (uint32_t)(bkr * BSTR + bc0) * 2;

    float acc[2][8][4];
#pragma unroll
    for (int mt = 0; mt < 2; mt++)
#pragma unroll
        for (int n = 0; n < 8; n++){ acc[mt][n][0]=acc[mt][n][1]=acc[mt][n][2]=acc[mt][n][3]=0.f; }

    uint32_t aOff0 = ((mg*32 + (lane & 15)) * ASTR + (lane >> 4) * 8) * 2;
    uint32_t aOff1 = ((mg*32 + 16 + (lane & 15)) * ASTR + (lane >> 4) * 8) * 2;
    uint32_t bT = ((lane & 15) * BSTR + (lane >> 4) * 8) * 2 + ng * 128;

    int nt = KP / 32;

#define ISSUE_TILE(BUFB, K0) do { \
    const bf16* _pa = Ahi + arbase + (K0); \
    const bf16* _pl = Alo + arbase + (K0); \
    cpa16((BUFB) + OFF_AHI + adst,      _pa); \
    cpa16((BUFB) + OFF_AHI + adst + 16, _pa + 8); \
    cpa16((BUFB) + OFF_ALO + adst,      _pl); \
    cpa16((BUFB) + OFF_ALO + adst + 16, _pl + 8); \
    const bf16* _pbh = Bh + bo + (size_t)(K0) * ldw; \
    const bf16* _pbl = Bl + bo + (size_t)(K0) * ldw; \
    cpa16((BUFB) + OFF_BHI + bdst,      _pbh); \
    cpa16((BUFB) + OFF_BHI + bdst + 16, _pbh + 8); \
    cpa16((BUFB) + OFF_BLO + bdst,      _pbl); \
    cpa16((BUFB) + OFF_BLO + bdst + 16, _pbl + 8); \
} while(0)

    ISSUE_TILE(sb, 0); CPA_COMMIT();
    if (nt > 1){ ISSUE_TILE(sb + BUFSZ, 32); CPA_COMMIT(); }

    int bufIdx = 0;
    for (int t = 0; t < nt; t++){
        if (t + 1 < nt) { CPA_WAIT1(); } else { CPA_WAIT0(); }
        __syncthreads();
        uint32_t bufb = sb + bufIdx * BUFSZ;
#pragma unroll
        for (int h = 0; h < 2; h++){
            uint32_t a0h0,a0h1,a0h2,a0h3, a0l0,a0l1,a0l2,a0l3;
            uint32_t a1h0,a1h1,a1h2,a1h3, a1l0,a1l1,a1l2,a1l3;
            ldsm4(a0h0,a0h1,a0h2,a0h3, bufb + OFF_AHI + aOff0 + h*32);
            ldsm4(a0l0,a0l1,a0l2,a0l3, bufb + OFF_ALO + aOff0 + h*32);
            ldsm4(a1h0,a1h1,a1h2,a1h3, bufb + OFF_AHI + aOff1 + h*32);
            ldsm4(a1l0,a1l1,a1l2,a1l3, bufb + OFF_ALO + aOff1 + h*32);
#pragma unroll
            for (int np = 0; np < 4; np++){
                uint32_t ba = bT + h*16*BSTR*2 + np*32;
                uint32_t bh0,bh1,bh2,bh3, bl0,bl1,bl2,bl3;
                ldsm4t(bh0,bh1,bh2,bh3, bufb + OFF_BHI + ba);
                ldsm4t(bl0,bl1,bl2,bl3, bufb + OFF_BLO + ba);
                mma16816(acc[0][2*np],   a0h0,a0h1,a0h2,a0h3, bh0,bh1);
                mma16816(acc[0][2*np],   a0h0,a0h1,a0h2,a0h3, bl0,bl1);
                mma16816(acc[0][2*np],   a0l0,a0l1,a0l2,a0l3, bh0,bh1);
                mma16816(acc[0][2*np+1], a0h0,a0h1,a0h2,a0h3, bh2,bh3);
                mma16816(acc[0][2*np+1], a0h0,a0h1,a0h2,a0h3, bl2,bl3);
                mma16816(acc[0][2*np+1], a0l0,a0l1,a0l2,a0l3, bh2,bh3);
                mma16816(acc[1][2*np],   a1h0,a1h1,a1h2,a1h3, bh0,bh1);
                mma16816(acc[1][2*np],   a1h0,a1h1,a1h2,a1h3, bl0,bl1);
                mma16816(acc[1][2*np],   a1l0,a1l1,a1l2,a1l3, bh0,bh1);
                mma16816(acc[1][2*np+1], a1h0,a1h1,a1h2,a1h3, bh2,bh3);
                mma16816(acc[1][2*np+1], a1h0,a1h1,a1h2,a1h3, bl2,bl3);
                mma16816(acc[1][2*np+1], a1l0,a1l1,a1l2,a1l3, bh2,bh3);
            }
        }
        if (t + 2 < nt){
            int nb = bufIdx + 2; if (nb >= 3) nb -= 3;
            ISSUE_TILE(sb + nb * BUFSZ, (t + 2) * 32); CPA_COMMIT();
        }
        bufIdx = (bufIdx == 2) ? 0 : bufIdx + 1;
    }
#undef ISSUE_TILE

    if (!SCORE) {
        float* od = out + (size_t)dir * M * ldw;
#pragma unroll
        for (int mt = 0; mt < 2; mt++){
            int r0 = m0 + mg*32 + mt*16 + g;
#pragma unroll
            for (int n = 0; n < 8; n++){
                int c = j0 + ng*64 + n*8 + t4*2;
                float b0 = __ldg(&bias[c]), b1 = __ldg(&bias[c+1]);
                float2 o0{acc[mt][n][0] + b0, acc[mt][n][1] + b1};
                float2 o1{acc[mt][n][2] + b0, acc[mt][n][3] + b1};
                *(float2*)&od[(size_t)r0 * ldw + c]     = o0;
                *(float2*)&od[(size_t)(r0+8) * ldw + c] = o1;
            }
        }
    } else {
#pragma unroll
        for (int mt = 0; mt < 2; mt++){
            float s0 = 0.f, s1 = 0.f;
#pragma unroll
            for (int n = 0; n < 8; n++){
                int c = j0 + ng*64 + n*8 + t4*2;
                float b0 = __ldg(&bias[c]), b1 = __ldg(&bias[c+1]);
                float c0 = __ldg(&ctx[c]),  c1 = __ldg(&ctx[c+1]);
                s0 += ftanh(acc[mt][n][0] + b0)*c0 + ftanh(acc[mt][n][1] + b1)*c1;
                s1 += ftanh(acc[mt][n][2] + b0)*c0 + ftanh(acc[mt][n][3] + b1)*c1;
            }
            s0 += __shfl_xor_sync(0xffffffffu, s0, 1); s0 += __shfl_xor_sync(0xffffffffu, s0, 2);
            s1 += __shfl_xor_sync(0xffffffffu, s1, 1); s1 += __shfl_xor_sync(0xffffffffu, s1, 2);
            if (t4 == 0){
                int r0 = m0 + mg*32 + mt*16 + g;
                int pslot = jb * 2 + ng;
                out[(size_t)pslot * M + r0]     = s0;
                out[(size_t)pslot * M + r0 + 8] = s1;
            }
        }
    }
}

// ---------------------------------------------------------------------------
// GRU scan (R14-proven: unsplit k-loop, x-loads batched after it)
// ---------------------------------------------------------------------------
template<int T, int G>
__global__ __launch_bounds__(256,2) void gru_scan_kernel(
    const float* __restrict__ xg,
    bf16* __restrict__ hb_hi, bf16* __restrict__ hb_lo,
    const float4* __restrict__ whp,
    const float* __restrict__ bhf, const float* __restrict__ bhb, int NS)
{
    constexpr int P = G / 2;
    __shared__ __align__(16) float sh[2][256][G];
    int j = threadIdx.x;
    int gpd = NS / G;
    int d  = blockIdx.x / gpd;
    int n0 = (blockIdx.x % gpd) * G;
    const float* bh = d ? bhb : bhf;
    const float4* Wp = whp + (size_t)d * 256 * 256;
    const float* xgd = xg + (size_t)d * NS * T * HD3;
    float bhr = bh[j], bhz = bh[256 + j], bhn = bh[512 + j];
    float hprev[G];
#pragma unroll
    for (int gg = 0; gg < G; gg++){ hprev[gg] = 0.f; sh[0][j][gg] = 0.f; }
    __syncthreads();

    int cur = 0;
    for (int tt = 0; tt < T; tt++) {
        int t = d ? (T - 1 - tt) : tt;
        ull ar[P], az[P], an[P];
#pragma unroll
        for (int p = 0; p < P; p++){
            ar[p] = pk2(bhr, bhr); az[p] = pk2(bhz, bhz); an[p] = pk2(bhn, bhn);
        }
        float4 w = Wp[j];
#pragma unroll 8
        for (int k = 0; k < 256; k++) {
            float4 wnext = Wp[(size_t)(k + 1) * 256 + j];
            ull wr2 = pk2(w.x, w.x), wz2 = pk2(w.y, w.y), wn2 = pk2(w.z, w.z);
            if constexpr ((G & 3) == 0) {
#pragma unroll
                for (int q = 0; q < P/2; q++){
                    ulonglong2 hq = *(const ulonglong2*)&sh[cur][k][4*q];
                    ar[2*q]   = fma2(wr2, hq.x, ar[2*q]);
                    az[2*q]   = fma2(wz2, hq.x, az[2*q]);
                    an[2*q]   = fma2(wn2, hq.x, an[2*q]);
                    ar[2*q+1] = fma2(wr2, hq.y, ar[2*q+1]);
                    az[2*q+1] = fma2(wz2, hq.y, az[2*q+1]);
                    an[2*q+1] = fma2(wn2, hq.y, an[2*q+1]);
                }
            } else {
#pragma unroll
                for (int p = 0; p < P; p++){
                    ull h2 = *(const ull*)&sh[cur][k][2*p];
                    ar[p] = fma2(wr2, h2, ar[p]);
                    az[p] = fma2(wz2, h2, az[p]);
                    an[p] = fma2(wn2, h2, an[p]);
                }
            }
            w = wnext;
        }
        int nxt = cur ^ 1;
        float xr[G], xz[G], xn[G];
#pragma unroll
        for (int gg = 0; gg < G; gg++){
            const float* xp = xgd + ((size_t)(n0 + gg) * T + t) * HD3;
            xr[gg] = xp[j]; xz[gg] = xp[256 + j]; xn[gg] = xp[512 + j];
        }
        float hnew[G];
#pragma unroll
        for (int p = 0; p < P; p++){
            float2 fr = upk2(ar[p]), fz = upk2(az[p]), fn = upk2(an[p]);
#pragma unroll
            for (int e = 0; e < 2; e++){
                int gg = 2*p + e;
                float hr = e ? fr.y : fr.x, hz = e ? fz.y : fz.x, hn = e ? fn.y : fn.x;
                float r = fsig(xr[gg] + hr), z = fsig(xz[gg] + hz);
                float n = ftanh(xn[gg] + r * hn);
                hnew[gg] = (1.f - z) * n + z * hprev[gg];
            }
        }
#pragma unroll
        for (int gg = 0; gg < G; gg++){
            float hv = hnew[gg];
            hprev[gg] = hv;
            sh[nxt][j][gg] = hv;
            size_t off = ((size_t)(n0 + gg) * T + t) * HD2 + d * 256 + j;
            bf16 bhv = __float2bfloat16_rn(hv);
            hb_hi[off] = bhv;
            hb_lo[off] = __float2bfloat16_rn(hv - __bfloat162float(bhv));
        }
        cur = nxt;
        __syncthreads();
    }
}

// ---------------------------------------------------------------------------
// Attention epilogue (proven, unchanged)
// ---------------------------------------------------------------------------
template<int T, bool FINAL>
__global__ __launch_bounds__(256) void attn_epi_kernel(
    const float* __restrict__ part,
    const bf16* __restrict__ h_hi, const bf16* __restrict__ h_lo,
    bf16* __restrict__ outv_hi, bf16* __restrict__ outv_lo,
    const float* __restrict__ outW,
    const float* __restrict__ outb,
    float* __restrict__ outFinal,
    int Mtot)
{
    __shared__ float sScore[T], sX[T], sSrt[T], sAtt[T];
    __shared__ float sTau, sMax;
    __shared__ float sDoc[512];
    int tid = threadIdx.x;
    int n = blockIdx.x;
    size_t hbase = (size_t)n * T * HD2;

    if (tid < T) {
        float s = 0.f;
#pragma unroll
        for (int jb = 0; jb < 8; jb++) s += part[(size_t)jb * Mtot + n * T + tid];
        sScore[tid] = s;
    }
    __syncthreads();
    if (tid == 0) {
        float mx = sScore[0];
        for (int t = 1; t < T; t++) mx = fmaxf(mx, sScore[t]);
        sMax = mx;
    }
    __syncthreads();
    if (tid < T) {
        float x = sScore[tid] - sMax;
        sX[tid] = x;
        int rank = 0;
        for (int u = 0; u < T; u++){
            float xu = sScore[u] - sMax;
            if (xu > x || (xu == x && u < tid)) rank++;
        }
        sSrt[rank] = x;
    }
    __syncthreads();
    if (tid == 0) {
        float cs = -1.f; int supp = 0; float csAt = 0.f;
        for (int k = 0; k < T; k++){
            cs += sSrt[k];
            if ((float)(k + 1) * sSrt[k] > cs) { supp = k + 1; csAt = cs; }
        }
        sTau = csAt / (float)supp;
    }
    __syncthreads();
    if (tid < T) sAtt[tid] = fmaxf(sX[tid] - sTau, 0.f);
    __syncthreads();
    {
        int jj = tid * 2;
        float ax = 0.f, ay = 0.f;
#pragma unroll 8
        for (int t = 0; t < T; t++){
            size_t off = hbase + (size_t)t * HD2 + jj;
            uint32_t ph = *(const uint32_t*)&h_hi[off];
            uint32_t pl = *(const uint32_t*)&h_lo[off];
            __nv_bfloat162 bh = *(__nv_bfloat162*)&ph;
            __nv_bfloat162 bl = *(__nv_bfloat162*)&pl;
            float hx = __bfloat162float(bh.x) + __bfloat162float(bl.x);
            float hy = __bfloat162float(bh.y) + __bfloat162float(bl.y);
            float a = sAtt[t];
            ax += a * hx; ay += a * hy;
        }
        if (FINAL){ sDoc[jj] = ax; sDoc[jj + 1] = ay; }
        else {
            size_t o = (size_t)n * HD2 + jj;
            bf16 hx = __float2bfloat16_rn(ax);
            bf16 hy = __float2bfloat16_rn(ay);
            __nv_bfloat162 hp = __halves2bfloat162(hx, hy);
            __nv_bfloat162 lp = __halves2bfloat162(
                __float2bfloat16_rn(ax - __bfloat162float(hx)),
                __float2bfloat16_rn(ay - __bfloat162float(hy)));
            *(uint32_t*)&outv_hi[o] = *(uint32_t*)&hp;
            *(uint32_t*)&outv_lo[o] = *(uint32_t*)&lp;
        }
    }
    if (FINAL) {
        __syncthreads();
        if (tid < 10) {
            float s = outb[tid];
            for (int jj2 = 0; jj2 < 512; jj2++) s += sDoc[jj2] * outW[jj2 * 10 + tid];
            outFinal[n * 10 + tid] = s;
        }
    }
}

extern "C" void kernel_launch(void* const* d_in, const int* in_sizes, int n_in,
                              void* d_out, int out_size) {
    const int*   tokens  = (const int*)  d_in[0];
    const float* emb     = (const float*)d_in[1];
    const float* w_Wx_f  = (const float*)d_in[2];
    const float* w_Wh_f  = (const float*)d_in[3];
    const float* w_bx_f  = (const float*)d_in[4];
    const float* w_bh_f  = (const float*)d_in[5];
    const float* w_Wx_b  = (const float*)d_in[6];
    const float* w_Wh_b  = (const float*)d_in[7];
    const float* w_bx_b  = (const float*)d_in[8];
    const float* w_bh_b  = (const float*)d_in[9];
    const float* w_lin_W = (const float*)d_in[10];
    const float* w_lin_b = (const float*)d_in[11];
    const float* w_ctx   = (const float*)d_in[12];
    const float* s_Wx_f  = (const float*)d_in[13];
    const float* s_Wh_f  = (const float*)d_in[14];
    const float* s_bx_f  = (const float*)d_in[15];
    const float* s_bh_f  = (const float*)d_in[16];
    const float* s_Wx_b  = (const float*)d_in[17];
    const float* s_Wh_b  = (const float*)d_in[18];
    const float* s_bx_b  = (const float*)d_in[19];
    const float* s_bh_b  = (const float*)d_in[20];
    const float* s_lin_W = (const float*)d_in[21];
    const float* s_lin_b = (const float*)d_in[22];
    const float* s_ctx   = (const float*)d_in[23];
    const float* out_W   = (const float*)d_in[24];
    const float* out_b   = (const float*)d_in[25];
    float* out = (float*)d_out;

    int V = in_sizes[1] / EDIM;

    float *p_xg, *p_xg2;
    float4 *p_whp, *p_whp2;
    bf16 *p_embH, *p_embL, *p_wxH, *p_wxL, *p_linH, *p_linL;
    bf16 *p_swxH, *p_swxL, *p_slinH, *p_slinL;
    bf16 *p_hbH, *p_hbL, *p_sbH, *p_sbL, *p_h2bH, *p_h2bL;
    cudaGetSymbolAddress((void**)&p_xg,   g_xg);
    cudaGetSymbolAddress((void**)&p_xg2,  g_xg2);
    cudaGetSymbolAddress((void**)&p_whp,  g_whp);
    cudaGetSymbolAddress((void**)&p_whp2, g_whp2);
    cudaGetSymbolAddress((void**)&p_embH, g_embC_hi);  cudaGetSymbolAddress((void**)&p_embL, g_embC_lo);
    cudaGetSymbolAddress((void**)&p_wxH,  g_wxC_hi);   cudaGetSymbolAddress((void**)&p_wxL,  g_wxC_lo);
    cudaGetSymbolAddress((void**)&p_linH, g_linC_hi);  cudaGetSymbolAddress((void**)&p_linL, g_linC_lo);
    cudaGetSymbolAddress((void**)&p_swxH, g_swxC_hi);  cudaGetSymbolAddress((void**)&p_swxL, g_swxC_lo);
    cudaGetSymbolAddress((void**)&p_slinH,g_slinC_hi); cudaGetSymbolAddress((void**)&p_slinL,g_slinC_lo);
    cudaGetSymbolAddress((void**)&p_hbH,  g_hb_hi);    cudaGetSymbolAddress((void**)&p_hbL,  g_hb_lo);
    cudaGetSymbolAddress((void**)&p_sbH,  g_sb_hi);    cudaGetSymbolAddress((void**)&p_sbL,  g_sb_lo);
    cudaGetSymbolAddress((void**)&p_h2bH, g_h2b_hi);   cudaGetSymbolAddress((void**)&p_h2bL, g_h2b_lo);

    cudaFuncSetAttribute(mma2_kernel<false>, cudaFuncAttributeMaxDynamicSharedMemorySize, GSMEM);
    cudaFuncSetAttribute(mma2_kernel<true>,  cudaFuncAttributeMaxDynamicSharedMemorySize, GSMEM);

    // 0. one-time conversions / repacks
    repack_wh_kernel<<<dim3(256,2), 256>>>(w_Wh_f, w_Wh_b, p_whp);
    repack_wh_kernel<<<dim3(256,2), 256>>>(s_Wh_f, s_Wh_b, p_whp2);
    {
        long long tot = (long long)V * EKP;
        conv_splitA_kernel<<<(unsigned)((tot + 255) / 256), 256>>>(emb, p_embH, p_embL, EDIM, EKP, tot);
    }
    conv_weights_kernel<<<dim3((HD2*HD3 + 255)/256, 6), 256>>>(
        w_Wx_f, w_Wx_b, w_lin_W, s_Wx_f, s_Wx_b, s_lin_W,
        p_wxH, p_wxL, p_linH, p_linL, p_swxH, p_swxL, p_slinH, p_slinL);
    // 1. word input gates (embedding gather fused)
    mma2_kernel<false><<<dim3(MWORD/128, 12), 256, GSMEM>>>(
        p_embH, p_embL, tokens, EKP, p_wxH, p_wxL, w_bx_f, w_bx_b, nullptr, p_xg, MWORD, 6);
    // 2. word BiGRU scan
    gru_scan_kernel<TW, 8><<<(NWSEQ/8)*2, 256>>>(
        p_xg, p_hbH, p_hbL, p_whp, w_bh_f, w_bh_b, NWSEQ);
    // 3. word rep GEMM fused into scores (partials into g_xg: 8 slots)
    mma2_kernel<true><<<dim3(MWORD/128, 4), 256, GSMEM>>>(
        p_hbH, p_hbL, nullptr, HD2, p_linH, p_linL, w_lin_b, w_lin_b, w_ctx, p_xg, MWORD, 4);
    // 4. word attention epilogue -> sentence vectors (bf16-split direct)
    attn_epi_kernel<TW, false><<<NWSEQ, 256>>>(
        p_xg, p_hbH, p_hbL, p_sbH, p_sbL, nullptr, nullptr, nullptr, MWORD);
    // 5. sentence input gates
    mma2_kernel<false><<<dim3(MSENT/128, 12), 256, GSMEM>>>(
        p_sbH, p_sbL, nullptr, HD2, p_swxH, p_swxL, s_bx_f, s_bx_b, nullptr, p_xg2, MSENT, 6);
    // 6. sentence BiGRU scan
    gru_scan_kernel<TSENT, 2><<<(NDOC/2)*2, 256>>>(
        p_xg2, p_h2bH, p_h2bL, p_whp2, s_bh_f, s_bh_b, NDOC);
    // 7. sentence rep+score GEMM (partials into g_xg2)
    mma2_kernel<true><<<dim3(MSENT/128, 4), 256, GSMEM>>>(
        p_h2bH, p_h2bL, nullptr, HD2, p_slinH, p_slinL, s_lin_b, s_lin_b, s_ctx, p_xg2, MSENT, 4);
    // 8. sentence attention + final classifier
    attn_epi_kernel<TSENT, true><<<NDOC, 256>>>(
        p_xg2, p_h2bH, p_h2bL, nullptr, nullptr, out_W, out_b, out, MSENT);
}